// round 8
// baseline (speedup 1.0000x reference)
#include <cuda_runtime.h>
#include <cuda_bf16.h>
#include <cstdint>

#define NN      65536
#define EE      1048576
#define IN_DIM  500
#define KPAD1   512
#define HID     256
#define OUTD    64
#define ALPHA   0.1f

// ---------------- static device scratch ----------------
__device__ __nv_bfloat16 g_h1h[(size_t)NN * HID];
__device__ __nv_bfloat16 g_h1l[(size_t)NN * HID];
__device__ __nv_bfloat16 g_h2h[(size_t)NN * HID];
__device__ __nv_bfloat16 g_h2l[(size_t)NN * HID];
__device__ float g_h0[(size_t)NN * OUTD];
__device__ float g_hA[(size_t)NN * OUTD];
__device__ float g_hB[(size_t)NN * OUTD];
__device__ __nv_bfloat16 g_B1h[(size_t)HID * KPAD1];
__device__ __nv_bfloat16 g_B1l[(size_t)HID * KPAD1];
__device__ __nv_bfloat16 g_B2h[(size_t)HID * HID];
__device__ __nv_bfloat16 g_B2l[(size_t)HID * HID];
__device__ __nv_bfloat16 g_B3h[(size_t)OUTD * HID];
__device__ __nv_bfloat16 g_B3l[(size_t)OUTD * HID];
__device__ int   g_rowoff[NN + 1];
__device__ int   g_cursor[NN];
__device__ int2  g_edge[EE];

// ---------------- helpers ----------------
__device__ __forceinline__ uint32_t smem_to_u32(const void* p) {
    uint32_t a;
    asm("{ .reg .u64 t; cvta.to.shared.u64 t, %1; cvt.u32.u64 %0, t; }" : "=r"(a) : "l"(p));
    return a;
}
__device__ __forceinline__ void ldmatrix_x4(uint32_t* r, uint32_t addr) {
    asm volatile("ldmatrix.sync.aligned.m8n8.x4.shared.b16 {%0,%1,%2,%3}, [%4];"
                 : "=r"(r[0]), "=r"(r[1]), "=r"(r[2]), "=r"(r[3]) : "r"(addr));
}
__device__ __forceinline__ void mma_bf16(float* c, const uint32_t* a, const uint32_t* b) {
    asm volatile(
        "mma.sync.aligned.m16n8k16.row.col.f32.bf16.bf16.f32 "
        "{%0,%1,%2,%3}, {%4,%5,%6,%7}, {%8,%9}, {%0,%1,%2,%3};"
        : "+f"(c[0]), "+f"(c[1]), "+f"(c[2]), "+f"(c[3])
        : "r"(a[0]), "r"(a[1]), "r"(a[2]), "r"(a[3]), "r"(b[0]), "r"(b[1]));
}
__device__ __forceinline__ void split_bf16(float a, __nv_bfloat16& hi, __nv_bfloat16& lo) {
    hi = __float2bfloat16_rn(a);
    lo = __float2bfloat16_rn(a - __bfloat162float(hi));
}
__device__ __forceinline__ uint32_t pack_bf16(__nv_bfloat16 x0, __nv_bfloat16 x1) {
    return ((uint32_t)__bfloat16_as_ushort(x1) << 16) | (uint32_t)__bfloat16_as_ushort(x0);
}

// ---------------- CSR construction ----------------
__global__ void zero_cursor_kernel() {
    int i = blockIdx.x * blockDim.x + threadIdx.x;
    if (i < NN) g_cursor[i] = 0;
}
__global__ void hist_kernel(const int* __restrict__ row) {
    int e = blockIdx.x * blockDim.x + threadIdx.x;
    if (e < EE) atomicAdd(&g_cursor[row[e]], 1);
}
__global__ void scan_kernel() {
    __shared__ int s[1024];
    int t = threadIdx.x;
    int base = t * 64;
    int sum = 0;
#pragma unroll 8
    for (int i = 0; i < 64; i++) sum += g_cursor[base + i];
    s[t] = sum;
    __syncthreads();
    for (int off = 1; off < 1024; off <<= 1) {
        int v = (t >= off) ? s[t - off] : 0;
        __syncthreads();
        s[t] += v;
        __syncthreads();
    }
    int running = s[t] - sum;
    for (int i = 0; i < 64; i++) {
        int d = g_cursor[base + i];
        g_rowoff[base + i] = running;
        g_cursor[base + i] = running;
        running += d;
    }
    if (t == 1023) g_rowoff[NN] = s[1023];
}
__global__ void scatter_kernel(const int* __restrict__ row, const int* __restrict__ col,
                               const float* __restrict__ w) {
    int e = blockIdx.x * blockDim.x + threadIdx.x;
    if (e < EE) {
        int p = atomicAdd(&g_cursor[row[e]], 1);
        g_edge[p] = make_int2(col[e], __float_as_int(0.9f * w[e]));
    }
}

// ---------------- weight transpose + pad + bf16 split ----------------
__global__ void splitw_kernel(const float* __restrict__ W,
                              __nv_bfloat16* __restrict__ Bh, __nv_bfloat16* __restrict__ Bl,
                              int K, int N, int Kpad) {
    int idx = blockIdx.x * blockDim.x + threadIdx.x;
    if (idx >= N * Kpad) return;
    int n = idx / Kpad, k = idx - n * Kpad;
    float v = (k < K) ? W[(size_t)k * N + n] : 0.f;
    __nv_bfloat16 hi, lo;
    split_bf16(v, hi, lo);
    Bh[idx] = hi;
    Bl[idx] = lo;
}

// ---------------- bf16-split mma.sync GEMM, warp tile 32x64 ----------------
// CTA tile 128 x (64*NWN). 4 warps in m, NWN warps in n. 128*NWN threads.
// BK=32, double-buffered smem, stride 80B per 32-elem row.
// NMAT = output matrix row stride; NT = 64*NWN = CTA n-tile.
template <int NMAT, int NWN, bool RELU, bool A_SPLIT_IN, bool OUT_SPLIT>
__global__ void __launch_bounds__(128 * NWN, (NWN == 1) ? 2 : 1)
gemm_mma_kernel(
    const float* __restrict__ A,
    const __nv_bfloat16* __restrict__ Ah, const __nv_bfloat16* __restrict__ Al,
    const __nv_bfloat16* __restrict__ Bh, const __nv_bfloat16* __restrict__ Bl,
    const float* __restrict__ bias,
    float* __restrict__ C,
    __nv_bfloat16* __restrict__ Ch, __nv_bfloat16* __restrict__ Cl,
    int K, int Kpad)
{
    constexpr int NTH   = 128 * NWN;       // threads
    constexpr int NT    = 64 * NWN;        // CTA n-tile
    constexpr int A_SP  = 128 * 80;        // bytes per A split tile (10240)
    constexpr int B_SP  = NT * 80;         // bytes per B split tile
    constexpr int SMAH  = 0;
    constexpr int SMAL  = A_SP;
    constexpr int SMBH  = 2 * A_SP;
    constexpr int SMBL  = 2 * A_SP + B_SP;
    constexpr int BUF   = 2 * A_SP + 2 * B_SP;
    constexpr int AF32  = 8 / NWN;         // fp32-A float4 slots per thread
    constexpr int ASP   = 4 / NWN;         // split-A uint4 slots per thread

    extern __shared__ char smem[];
    uint32_t sbase = smem_to_u32(smem);

    int tid  = threadIdx.x;
    int wid  = tid >> 5;
    int lane = tid & 31;
    int m0 = blockIdx.x * 128;
    int n0 = blockIdx.y * NT;
    int warp_m = wid & 3;
    int warp_n = wid >> 2;                 // 0..NWN-1

    float acc[2][8][4];
#pragma unroll
    for (int i = 0; i < 2; i++)
#pragma unroll
        for (int j = 0; j < 8; j++)
#pragma unroll
            for (int r = 0; r < 4; r++) acc[i][j][r] = 0.f;

    const int nch = Kpad >> 5;

    // staging regs
    float4 ga[AF32];
    uint4  gah[ASP], gal[ASP];
    uint4  gbh[2], gbl[2];

#define LOAD_GLOBAL(CH) do { \
    int k0_ = (CH) << 5; \
    if (A_SPLIT_IN) { \
        _Pragma("unroll") \
        for (int i = 0; i < ASP; i++) { \
            int slot = tid + i * NTH; \
            size_t off = (size_t)(m0 + (slot >> 2)) * Kpad + k0_ + (slot & 3) * 8; \
            gah[i] = *(const uint4*)(Ah + off); \
            gal[i] = *(const uint4*)(Al + off); \
        } \
    } else { \
        _Pragma("unroll") \
        for (int i = 0; i < AF32; i++) { \
            int slot = tid + i * NTH; \
            int kg = k0_ + (slot & 7) * 4; \
            if (kg < K) ga[i] = *(const float4*)(A + (size_t)(m0 + (slot >> 3)) * K + kg); \
            else        ga[i] = make_float4(0.f, 0.f, 0.f, 0.f); \
        } \
    } \
    _Pragma("unroll") \
    for (int i = 0; i < 2; i++) { \
        int slot = tid + i * NTH; \
        size_t off = (size_t)(n0 + (slot >> 2)) * Kpad + k0_ + (slot & 3) * 8; \
        gbh[i] = *(const uint4*)(Bh + off); \
        gbl[i] = *(const uint4*)(Bl + off); \
    } \
} while (0)

#define STORE_SMEM(BUFI) do { \
    char* tb = smem + (BUFI) * BUF; \
    if (A_SPLIT_IN) { \
        _Pragma("unroll") \
        for (int i = 0; i < ASP; i++) { \
            int slot = tid + i * NTH; \
            int off = (slot >> 2) * 80 + (slot & 3) * 16; \
            *(uint4*)(tb + SMAH + off) = gah[i]; \
            *(uint4*)(tb + SMAL + off) = gal[i]; \
        } \
    } else { \
        _Pragma("unroll") \
        for (int i = 0; i < AF32; i++) { \
            int slot = tid + i * NTH; \
            __nv_bfloat16 hx, lx, hy, ly, hz, lz, hw, lw; \
            split_bf16(ga[i].x, hx, lx); split_bf16(ga[i].y, hy, ly); \
            split_bf16(ga[i].z, hz, lz); split_bf16(ga[i].w, hw, lw); \
            uint2 ph_ = make_uint2(pack_bf16(hx, hy), pack_bf16(hz, hw)); \
            uint2 pl_ = make_uint2(pack_bf16(lx, ly), pack_bf16(lz, lw)); \
            int off = (slot >> 3) * 80 + (slot & 7) * 8; \
            *(uint2*)(tb + SMAH + off) = ph_; \
            *(uint2*)(tb + SMAL + off) = pl_; \
        } \
    } \
    _Pragma("unroll") \
    for (int i = 0; i < 2; i++) { \
        int slot = tid + i * NTH; \
        int off = (slot >> 2) * 80 + (slot & 3) * 16; \
        *(uint4*)(tb + SMBH + off) = gbh[i]; \
        *(uint4*)(tb + SMBL + off) = gbl[i]; \
    } \
} while (0)

    LOAD_GLOBAL(0);
    STORE_SMEM(0);
    __syncthreads();

    for (int ch = 0; ch < nch; ch++) {
        if (ch + 1 < nch) LOAD_GLOBAL(ch + 1);

        uint32_t ub = sbase + (ch & 1) * BUF;
#pragma unroll
        for (int kk = 0; kk < 32; kk += 16) {
            uint32_t afr[2][2][4];     // [split][mt]
            uint32_t bfr[2][4][4];     // [split][np]
            {
                int rowA = warp_m * 32 + (lane & 15);
                int colA = kk + ((lane >> 4) << 3);
#pragma unroll
                for (int mt = 0; mt < 2; mt++) {
                    uint32_t ad = ub + (uint32_t)((rowA + mt * 16) * 80 + colA * 2);
                    ldmatrix_x4(afr[0][mt], ad + SMAH);
                    ldmatrix_x4(afr[1][mt], ad + SMAL);
                }
                int rowB = warp_n * 64 + ((lane >> 4) << 3) + (lane & 7);
                int colB = kk + (((lane >> 3) & 1) << 3);
#pragma unroll
                for (int np = 0; np < 4; np++) {
                    uint32_t bd = ub + (uint32_t)((rowB + np * 16) * 80 + colB * 2);
                    ldmatrix_x4(bfr[0][np], bd + SMBH);
                    ldmatrix_x4(bfr[1][np], bd + SMBL);
                }
            }
#pragma unroll
            for (int mt = 0; mt < 2; mt++)
#pragma unroll
                for (int nt = 0; nt < 8; nt++) {
                    int np = nt >> 1, sub = (nt & 1) * 2;
                    mma_bf16(acc[mt][nt], afr[0][mt], &bfr[0][np][sub]);
                    mma_bf16(acc[mt][nt], afr[0][mt], &bfr[1][np][sub]);
                    mma_bf16(acc[mt][nt], afr[1][mt], &bfr[0][np][sub]);
                }
        }
        __syncthreads();
        if (ch + 1 < nch) {
            STORE_SMEM((ch + 1) & 1);
        }
        __syncthreads();
    }

    // ---- epilogue ----
    int rb   = m0 + warp_m * 32 + (lane >> 2);
    int colb = n0 + warp_n * 64 + (lane & 3) * 2;
#pragma unroll
    for (int mt = 0; mt < 2; mt++)
#pragma unroll
        for (int nt = 0; nt < 8; nt++) {
            int col = colb + nt * 8;
            float b0 = __ldg(bias + col);
            float b1 = __ldg(bias + col + 1);
#pragma unroll
            for (int rp = 0; rp < 2; rp++) {
                int row = rb + mt * 16 + rp * 8;
                float v0 = acc[mt][nt][rp * 2 + 0] + b0;
                float v1 = acc[mt][nt][rp * 2 + 1] + b1;
                if (RELU) { v0 = fmaxf(v0, 0.f); v1 = fmaxf(v1, 0.f); }
                size_t off = (size_t)row * NMAT + col;
                if (OUT_SPLIT) {
                    __nv_bfloat16 h0_, l0_, h1_, l1_;
                    split_bf16(v0, h0_, l0_);
                    split_bf16(v1, h1_, l1_);
                    *(uint32_t*)(Ch + off) = pack_bf16(h0_, h1_);
                    *(uint32_t*)(Cl + off) = pack_bf16(l0_, l1_);
                } else {
                    C[off]     = v0;
                    C[off + 1] = v1;
                }
            }
        }
}

// ---------------- propagation ----------------
__global__ void __launch_bounds__(256) prop_kernel(
    const float* __restrict__ hsrc, const float* __restrict__ h0,
    float* __restrict__ hdst)
{
    int warp = (blockIdx.x * blockDim.x + threadIdx.x) >> 5;
    if (warp >= NN) return;
    int lane = threadIdx.x & 31;
    int half = lane >> 4;
    int sub  = lane & 15;

    int beg = g_rowoff[warp];
    int end = g_rowoff[warp + 1];

    float4 acc = make_float4(0.f, 0.f, 0.f, 0.f);
    for (int idx = beg + half; idx < end; idx += 2) {
        int2 ed = g_edge[idx];
        float w = __int_as_float(ed.y);
        float4 hv = *(const float4*)(hsrc + (size_t)ed.x * OUTD + sub * 4);
        acc.x = fmaf(hv.x, w, acc.x);
        acc.y = fmaf(hv.y, w, acc.y);
        acc.z = fmaf(hv.z, w, acc.z);
        acc.w = fmaf(hv.w, w, acc.w);
    }
    __syncwarp();
    acc.x += __shfl_down_sync(0xffffffffu, acc.x, 16);
    acc.y += __shfl_down_sync(0xffffffffu, acc.y, 16);
    acc.z += __shfl_down_sync(0xffffffffu, acc.z, 16);
    acc.w += __shfl_down_sync(0xffffffffu, acc.w, 16);

    if (half == 0) {
        float4 h0v = *(const float4*)(h0 + (size_t)warp * OUTD + sub * 4);
        float4 outv;
        outv.x = acc.x + ALPHA * h0v.x;
        outv.y = acc.y + ALPHA * h0v.y;
        outv.z = acc.z + ALPHA * h0v.z;
        outv.w = acc.w + ALPHA * h0v.w;
        *(float4*)(hdst + (size_t)warp * OUTD + sub * 4) = outv;
    }
}

// ---------------- host launcher ----------------
extern "C" void kernel_launch(void* const* d_in, const int* in_sizes, int n_in,
                              void* d_out, int out_size)
{
    const float* x    = (const float*)d_in[0];
    const float* W1   = (const float*)d_in[1];
    const float* b1   = (const float*)d_in[2];
    const float* W2   = (const float*)d_in[3];
    const float* b2   = (const float*)d_in[4];
    const float* W3   = (const float*)d_in[5];
    const float* b3   = (const float*)d_in[6];
    const float* ew   = (const float*)d_in[7];
    const int*   erow = (const int*)d_in[8];
    const int*   ecol = (const int*)d_in[9];

    float *h0, *hA, *hB;
    __nv_bfloat16 *h1h, *h1l, *h2h, *h2l;
    __nv_bfloat16 *b1h, *b1l, *b2h, *b2l, *b3h, *b3l;
    cudaGetSymbolAddress((void**)&h1h, g_h1h);
    cudaGetSymbolAddress((void**)&h1l, g_h1l);
    cudaGetSymbolAddress((void**)&h2h, g_h2h);
    cudaGetSymbolAddress((void**)&h2l, g_h2l);
    cudaGetSymbolAddress((void**)&h0, g_h0);
    cudaGetSymbolAddress((void**)&hA, g_hA);
    cudaGetSymbolAddress((void**)&hB, g_hB);
    cudaGetSymbolAddress((void**)&b1h, g_B1h);
    cudaGetSymbolAddress((void**)&b1l, g_B1l);
    cudaGetSymbolAddress((void**)&b2h, g_B2h);
    cudaGetSymbolAddress((void**)&b2l, g_B2l);
    cudaGetSymbolAddress((void**)&b3h, g_B3h);
    cudaGetSymbolAddress((void**)&b3l, g_B3l);

    // smem: NWN=2 -> buffer 40960, total 81920 ; NWN=1 -> buffer 30720, total 61440
    const int SMEM_W2 = 2 * (2 * 128 * 80 + 2 * 128 * 80);   // 81920
    const int SMEM_W1 = 2 * (2 * 128 * 80 + 2 * 64 * 80);    // 61440
    cudaFuncSetAttribute(gemm_mma_kernel<256, 2, true,  false, true >, cudaFuncAttributeMaxDynamicSharedMemorySize, SMEM_W2);
    cudaFuncSetAttribute(gemm_mma_kernel<256, 2, true,  true,  true >, cudaFuncAttributeMaxDynamicSharedMemorySize, SMEM_W2);
    cudaFuncSetAttribute(gemm_mma_kernel<64,  1, false, true,  false>, cudaFuncAttributeMaxDynamicSharedMemorySize, SMEM_W1);

    // --- weight transpose + split ---
    splitw_kernel<<<(HID * KPAD1 + 255) / 256, 256>>>(W1, b1h, b1l, IN_DIM, HID, KPAD1);
    splitw_kernel<<<(HID * HID + 255) / 256, 256>>>(W2, b2h, b2l, HID, HID, HID);
    splitw_kernel<<<(OUTD * HID + 255) / 256, 256>>>(W3, b3h, b3l, HID, OUTD, HID);

    // --- MLP on tensor cores (bf16 2-term split, fp32 accumulate) ---
    gemm_mma_kernel<256, 2, true,  false, true ><<<dim3(NN / 128, 2), 256, SMEM_W2>>>(
        x, nullptr, nullptr, b1h, b1l, b1, nullptr, h1h, h1l, IN_DIM, KPAD1);
    gemm_mma_kernel<256, 2, true,  true,  true ><<<dim3(NN / 128, 2), 256, SMEM_W2>>>(
        nullptr, h1h, h1l, b2h, b2l, b2, nullptr, h2h, h2l, HID, HID);
    gemm_mma_kernel<64,  1, false, true,  false><<<dim3(NN / 128, 1), 128, SMEM_W1>>>(
        nullptr, h2h, h2l, b3h, b3l, b3, h0, nullptr, nullptr, HID, HID);

    // --- CSR build ---
    zero_cursor_kernel<<<NN / 256, 256>>>();
    hist_kernel<<<EE / 256, 256>>>(erow);
    scan_kernel<<<1, 1024>>>();
    scatter_kernel<<<EE / 256, 256>>>(erow, ecol, ew);

    // --- K=10 propagation steps ---
    float* out = (float*)d_out;
    const float* src = h0;
    for (int s = 0; s < 10; s++) {
        float* dst = (s == 9) ? out : ((s & 1) ? hB : hA);
        prop_kernel<<<(NN * 32) / 256, 256>>>(src, h0, dst);
        src = dst;
    }
}

// round 9
// speedup vs baseline: 1.1451x; 1.1451x over previous
#include <cuda_runtime.h>
#include <cuda_bf16.h>
#include <cuda_fp16.h>
#include <cstdint>

#define NN      65536
#define EE      1048576
#define IN_DIM  500
#define KPAD1   512
#define HID     256
#define OUTD    64
#define ALPHA   0.1f

// ---------------- static device scratch ----------------
__device__ __half g_h1f[(size_t)NN * HID];              // layer-1 out, fp16
__device__ __nv_bfloat16 g_h2h[(size_t)NN * HID];       // layer-2 out, split bf16
__device__ __nv_bfloat16 g_h2l[(size_t)NN * HID];
__device__ float g_h0[(size_t)NN * OUTD];
__device__ float g_hA[(size_t)NN * OUTD];
__device__ float g_hB[(size_t)NN * OUTD];
__device__ __half g_B1f[(size_t)HID * KPAD1];           // W1^T fp16 padded
__device__ __half g_B2f[(size_t)HID * HID];             // W2^T fp16
__device__ __nv_bfloat16 g_B3h[(size_t)OUTD * HID];     // W3^T split bf16
__device__ __nv_bfloat16 g_B3l[(size_t)OUTD * HID];
__device__ int   g_rowoff[NN + 1];
__device__ int   g_cursor[NN];
__device__ int2  g_edge[EE];

// ---------------- helpers ----------------
__device__ __forceinline__ uint32_t smem_to_u32(const void* p) {
    uint32_t a;
    asm("{ .reg .u64 t; cvta.to.shared.u64 t, %1; cvt.u32.u64 %0, t; }" : "=r"(a) : "l"(p));
    return a;
}
__device__ __forceinline__ void ldmatrix_x4(uint32_t* r, uint32_t addr) {
    asm volatile("ldmatrix.sync.aligned.m8n8.x4.shared.b16 {%0,%1,%2,%3}, [%4];"
                 : "=r"(r[0]), "=r"(r[1]), "=r"(r[2]), "=r"(r[3]) : "r"(addr));
}
__device__ __forceinline__ void mma_bf16(float* c, const uint32_t* a, const uint32_t* b) {
    asm volatile(
        "mma.sync.aligned.m16n8k16.row.col.f32.bf16.bf16.f32 "
        "{%0,%1,%2,%3}, {%4,%5,%6,%7}, {%8,%9}, {%0,%1,%2,%3};"
        : "+f"(c[0]), "+f"(c[1]), "+f"(c[2]), "+f"(c[3])
        : "r"(a[0]), "r"(a[1]), "r"(a[2]), "r"(a[3]), "r"(b[0]), "r"(b[1]));
}
__device__ __forceinline__ void mma_fp16(float* c, const uint32_t* a, const uint32_t* b) {
    asm volatile(
        "mma.sync.aligned.m16n8k16.row.col.f32.f16.f16.f32 "
        "{%0,%1,%2,%3}, {%4,%5,%6,%7}, {%8,%9}, {%0,%1,%2,%3};"
        : "+f"(c[0]), "+f"(c[1]), "+f"(c[2]), "+f"(c[3])
        : "r"(a[0]), "r"(a[1]), "r"(a[2]), "r"(a[3]), "r"(b[0]), "r"(b[1]));
}
__device__ __forceinline__ void split_bf16(float a, __nv_bfloat16& hi, __nv_bfloat16& lo) {
    hi = __float2bfloat16_rn(a);
    lo = __float2bfloat16_rn(a - __bfloat162float(hi));
}
__device__ __forceinline__ uint32_t pack_bf16(__nv_bfloat16 x0, __nv_bfloat16 x1) {
    return ((uint32_t)__bfloat16_as_ushort(x1) << 16) | (uint32_t)__bfloat16_as_ushort(x0);
}
__device__ __forceinline__ uint32_t pack_h16(__half x0, __half x1) {
    return ((uint32_t)__half_as_ushort(x1) << 16) | (uint32_t)__half_as_ushort(x0);
}

// ---------------- CSR construction ----------------
__global__ void zero_cursor_kernel() {
    int i = blockIdx.x * blockDim.x + threadIdx.x;
    if (i < NN) g_cursor[i] = 0;
}
__global__ void hist_kernel(const int* __restrict__ row) {
    int e = blockIdx.x * blockDim.x + threadIdx.x;
    if (e < EE) atomicAdd(&g_cursor[row[e]], 1);
}
__global__ void scan_kernel() {
    __shared__ int s[1024];
    int t = threadIdx.x;
    int base = t * 64;
    int sum = 0;
#pragma unroll 8
    for (int i = 0; i < 64; i++) sum += g_cursor[base + i];
    s[t] = sum;
    __syncthreads();
    for (int off = 1; off < 1024; off <<= 1) {
        int v = (t >= off) ? s[t - off] : 0;
        __syncthreads();
        s[t] += v;
        __syncthreads();
    }
    int running = s[t] - sum;
    for (int i = 0; i < 64; i++) {
        int d = g_cursor[base + i];
        g_rowoff[base + i] = running;
        g_cursor[base + i] = running;
        running += d;
    }
    if (t == 1023) g_rowoff[NN] = s[1023];
}
__global__ void scatter_kernel(const int* __restrict__ row, const int* __restrict__ col,
                               const float* __restrict__ w) {
    int e = blockIdx.x * blockDim.x + threadIdx.x;
    if (e < EE) {
        int p = atomicAdd(&g_cursor[row[e]], 1);
        g_edge[p] = make_int2(col[e], __float_as_int(0.9f * w[e]));
    }
}

// ---------------- weight prep: transpose + pad ----------------
__global__ void splitw_bf16_kernel(const float* __restrict__ W,
                                   __nv_bfloat16* __restrict__ Bh, __nv_bfloat16* __restrict__ Bl,
                                   int K, int N, int Kpad) {
    int idx = blockIdx.x * blockDim.x + threadIdx.x;
    if (idx >= N * Kpad) return;
    int n = idx / Kpad, k = idx - n * Kpad;
    float v = (k < K) ? W[(size_t)k * N + n] : 0.f;
    __nv_bfloat16 hi, lo;
    split_bf16(v, hi, lo);
    Bh[idx] = hi;
    Bl[idx] = lo;
}
__global__ void w_fp16_kernel(const float* __restrict__ W, __half* __restrict__ Bf,
                              int K, int N, int Kpad) {
    int idx = blockIdx.x * blockDim.x + threadIdx.x;
    if (idx >= N * Kpad) return;
    int n = idx / Kpad, k = idx - n * Kpad;
    float v = (k < K) ? W[(size_t)k * N + n] : 0.f;
    Bf[idx] = __float2half_rn(v);
}

// ================= fp16 single-term GEMM =================
// CTA 128x64, BK=32, 8 warps 4(m)x2(n), warp 32x32, double-buffered, occ 2.
// A_FP32_IN: A fp32 (convert in-kernel); else A fp16 [.,Kpad].
// OUT_FP16:  C fp16; else C split-bf16 (Ch,Cl).
#define F_SA    0
#define F_SB    10240
#define F_BUF   15360
#define F_SMEM  (2 * F_BUF)

template <int NMAT, bool RELU, bool A_FP32_IN, bool OUT_FP16>
__global__ void __launch_bounds__(256, 2) gemm_fp16_kernel(
    const float* __restrict__ A, const __half* __restrict__ Af,
    const __half* __restrict__ Bf, const float* __restrict__ bias,
    __half* __restrict__ Cf,
    __nv_bfloat16* __restrict__ Ch, __nv_bfloat16* __restrict__ Cl,
    int K, int Kpad)
{
    extern __shared__ char smem[];
    uint32_t sbase = smem_to_u32(smem);

    int tid  = threadIdx.x;
    int wid  = tid >> 5;
    int lane = tid & 31;
    int m0 = blockIdx.x * 128;
    int n0 = blockIdx.y * 64;
    int warp_m = wid & 3;
    int warp_n = wid >> 2;

    float acc[2][4][4];
#pragma unroll
    for (int i = 0; i < 2; i++)
#pragma unroll
        for (int j = 0; j < 4; j++)
#pragma unroll
            for (int r = 0; r < 4; r++) acc[i][j][r] = 0.f;

    const int nch = Kpad >> 5;

    float4 ga[4];      // fp32 A path
    uint4  gaf[2];     // fp16 A path
    uint4  gb;

#define F_LOAD(CH) do { \
    int k0_ = (CH) << 5; \
    if (A_FP32_IN) { \
        _Pragma("unroll") \
        for (int i = 0; i < 4; i++) { \
            int slot = tid + i * 256; \
            int kg = k0_ + (slot & 7) * 4; \
            if (kg + 3 < K) ga[i] = *(const float4*)(A + (size_t)(m0 + (slot >> 3)) * K + kg); \
            else            ga[i] = make_float4(0.f, 0.f, 0.f, 0.f); \
        } \
    } else { \
        _Pragma("unroll") \
        for (int i = 0; i < 2; i++) { \
            int slot = tid + i * 256; \
            gaf[i] = *(const uint4*)(Af + (size_t)(m0 + (slot >> 2)) * Kpad + k0_ + (slot & 3) * 8); \
        } \
    } \
    gb = *(const uint4*)(Bf + (size_t)(n0 + (tid >> 2)) * Kpad + k0_ + (tid & 3) * 8); \
} while (0)

#define F_STORE(BUFI) do { \
    char* tb = smem + (BUFI) * F_BUF; \
    if (A_FP32_IN) { \
        _Pragma("unroll") \
        for (int i = 0; i < 4; i++) { \
            int slot = tid + i * 256; \
            uint2 p_; \
            p_.x = pack_h16(__float2half_rn(ga[i].x), __float2half_rn(ga[i].y)); \
            p_.y = pack_h16(__float2half_rn(ga[i].z), __float2half_rn(ga[i].w)); \
            *(uint2*)(tb + F_SA + (slot >> 3) * 80 + (slot & 7) * 8) = p_; \
        } \
    } else { \
        _Pragma("unroll") \
        for (int i = 0; i < 2; i++) { \
            int slot = tid + i * 256; \
            *(uint4*)(tb + F_SA + (slot >> 2) * 80 + (slot & 3) * 16) = gaf[i]; \
        } \
    } \
    *(uint4*)(tb + F_SB + (tid >> 2) * 80 + (tid & 3) * 16) = gb; \
} while (0)

    F_LOAD(0);
    F_STORE(0);
    __syncthreads();

    for (int ch = 0; ch < nch; ch++) {
        if (ch + 1 < nch) F_LOAD(ch + 1);

        uint32_t ub = sbase + (ch & 1) * F_BUF;
#pragma unroll
        for (int kk = 0; kk < 32; kk += 16) {
            uint32_t afr[2][4];
            uint32_t bfr[2][4];
            {
                int rowA = warp_m * 32 + (lane & 15);
                int colA = kk + ((lane >> 4) << 3);
#pragma unroll
                for (int mt = 0; mt < 2; mt++)
                    ldmatrix_x4(afr[mt], ub + (uint32_t)(F_SA + (rowA + mt * 16) * 80 + colA * 2));
                int rowB = warp_n * 32 + ((lane >> 4) << 3) + (lane & 7);
                int colB = kk + (((lane >> 3) & 1) << 3);
#pragma unroll
                for (int np = 0; np < 2; np++)
                    ldmatrix_x4(bfr[np], ub + (uint32_t)(F_SB + (rowB + np * 16) * 80 + colB * 2));
            }
#pragma unroll
            for (int mt = 0; mt < 2; mt++)
#pragma unroll
                for (int nt = 0; nt < 4; nt++) {
                    int np = nt >> 1, sub = (nt & 1) * 2;
                    mma_fp16(acc[mt][nt], afr[mt], &bfr[np][sub]);
                }
        }
        __syncthreads();
        if (ch + 1 < nch) {
            F_STORE((ch + 1) & 1);
        }
        __syncthreads();
    }

    // ---- epilogue ----
    int rb   = m0 + warp_m * 32 + (lane >> 2);
    int colb = n0 + warp_n * 32 + (lane & 3) * 2;
#pragma unroll
    for (int mt = 0; mt < 2; mt++)
#pragma unroll
        for (int nt = 0; nt < 4; nt++) {
            int col = colb + nt * 8;
            float b0 = __ldg(bias + col);
            float b1 = __ldg(bias + col + 1);
#pragma unroll
            for (int rp = 0; rp < 2; rp++) {
                int row = rb + mt * 16 + rp * 8;
                float v0 = acc[mt][nt][rp * 2 + 0] + b0;
                float v1 = acc[mt][nt][rp * 2 + 1] + b1;
                if (RELU) { v0 = fmaxf(v0, 0.f); v1 = fmaxf(v1, 0.f); }
                size_t off = (size_t)row * NMAT + col;
                if (OUT_FP16) {
                    *(uint32_t*)(Cf + off) = pack_h16(__float2half_rn(v0), __float2half_rn(v1));
                } else {
                    __nv_bfloat16 h0_, l0_, h1_, l1_;
                    split_bf16(v0, h0_, l0_);
                    split_bf16(v1, h1_, l1_);
                    *(uint32_t*)(Ch + off) = pack_bf16(h0_, h1_);
                    *(uint32_t*)(Cl + off) = pack_bf16(l0_, l1_);
                }
            }
        }
}

// ================= bf16 3-term GEMM (round-7 proven, used for GEMM3) =================
#define SM_AH   0
#define SM_AL   10240
#define SM_BH   20480
#define SM_BL   25600
#define SM_BUF  30720
#define GEMM_SMEM (2 * SM_BUF)

template <int N_, bool RELU>
__global__ void __launch_bounds__(256, 2) gemm_bf16x3_kernel(
    const __nv_bfloat16* __restrict__ Ah, const __nv_bfloat16* __restrict__ Al,
    const __nv_bfloat16* __restrict__ Bh, const __nv_bfloat16* __restrict__ Bl,
    const float* __restrict__ bias, float* __restrict__ C,
    int Kpad)
{
    extern __shared__ char smem[];
    uint32_t sbase = smem_to_u32(smem);

    int tid  = threadIdx.x;
    int wid  = tid >> 5;
    int lane = tid & 31;
    int m0 = blockIdx.x * 128;
    int n0 = blockIdx.y * 64;
    int warp_m = wid & 3;
    int warp_n = wid >> 2;

    float acc[2][4][4];
#pragma unroll
    for (int i = 0; i < 2; i++)
#pragma unroll
        for (int j = 0; j < 4; j++)
#pragma unroll
            for (int r = 0; r < 4; r++) acc[i][j][r] = 0.f;

    const int nch = Kpad >> 5;

    uint4 gah[2], gal[2];
    uint4 gbh, gbl;

#define G3_LOAD(CH) do { \
    int k0_ = (CH) << 5; \
    _Pragma("unroll") \
    for (int i = 0; i < 2; i++) { \
        int slot = tid + i * 256; \
        size_t off = (size_t)(m0 + (slot >> 2)) * Kpad + k0_ + (slot & 3) * 8; \
        gah[i] = *(const uint4*)(Ah + off); \
        gal[i] = *(const uint4*)(Al + off); \
    } \
    { \
        size_t off = (size_t)(n0 + (tid >> 2)) * Kpad + k0_ + (tid & 3) * 8; \
        gbh = *(const uint4*)(Bh + off); \
        gbl = *(const uint4*)(Bl + off); \
    } \
} while (0)

#define G3_STORE(BUFI) do { \
    char* tb = smem + (BUFI) * SM_BUF; \
    _Pragma("unroll") \
    for (int i = 0; i < 2; i++) { \
        int slot = tid + i * 256; \
        int off = (slot >> 2) * 80 + (slot & 3) * 16; \
        *(uint4*)(tb + SM_AH + off) = gah[i]; \
        *(uint4*)(tb + SM_AL + off) = gal[i]; \
    } \
    { \
        int off = (tid >> 2) * 80 + (tid & 3) * 16; \
        *(uint4*)(tb + SM_BH + off) = gbh; \
        *(uint4*)(tb + SM_BL + off) = gbl; \
    } \
} while (0)

    G3_LOAD(0);
    G3_STORE(0);
    __syncthreads();

    for (int ch = 0; ch < nch; ch++) {
        if (ch + 1 < nch) G3_LOAD(ch + 1);

        uint32_t ub = sbase + (ch & 1) * SM_BUF;
#pragma unroll
        for (int kk = 0; kk < 32; kk += 16) {
            uint32_t afr[2][2][4];
            uint32_t bfr[2][2][4];
            {
                int rowA = warp_m * 32 + (lane & 15);
                int colA = kk + ((lane >> 4) << 3);
#pragma unroll
                for (int mt = 0; mt < 2; mt++) {
                    uint32_t ad = ub + (uint32_t)((rowA + mt * 16) * 80 + colA * 2);
                    ldmatrix_x4(afr[0][mt], ad + SM_AH);
                    ldmatrix_x4(afr[1][mt], ad + SM_AL);
                }
                int rowB = warp_n * 32 + ((lane >> 4) << 3) + (lane & 7);
                int colB = kk + (((lane >> 3) & 1) << 3);
#pragma unroll
                for (int np = 0; np < 2; np++) {
                    uint32_t bd = ub + (uint32_t)((rowB + np * 16) * 80 + colB * 2);
                    ldmatrix_x4(bfr[0][np], bd + SM_BH);
                    ldmatrix_x4(bfr[1][np], bd + SM_BL);
                }
            }
#pragma unroll
            for (int mt = 0; mt < 2; mt++)
#pragma unroll
                for (int nt = 0; nt < 4; nt++) {
                    int np = nt >> 1, sub = (nt & 1) * 2;
                    mma_bf16(acc[mt][nt], afr[0][mt], &bfr[0][np][sub]);
                    mma_bf16(acc[mt][nt], afr[0][mt], &bfr[1][np][sub]);
                    mma_bf16(acc[mt][nt], afr[1][mt], &bfr[0][np][sub]);
                }
        }
        __syncthreads();
        if (ch + 1 < nch) {
            G3_STORE((ch + 1) & 1);
        }
        __syncthreads();
    }

    int rb   = m0 + warp_m * 32 + (lane >> 2);
    int colb = n0 + warp_n * 32 + (lane & 3) * 2;
#pragma unroll
    for (int mt = 0; mt < 2; mt++)
#pragma unroll
        for (int nt = 0; nt < 4; nt++) {
            int col = colb + nt * 8;
            float b0 = __ldg(bias + col);
            float b1 = __ldg(bias + col + 1);
#pragma unroll
            for (int rp = 0; rp < 2; rp++) {
                int row = rb + mt * 16 + rp * 8;
                float v0 = acc[mt][nt][rp * 2 + 0] + b0;
                float v1 = acc[mt][nt][rp * 2 + 1] + b1;
                if (RELU) { v0 = fmaxf(v0, 0.f); v1 = fmaxf(v1, 0.f); }
                size_t off = (size_t)row * N_ + col;
                C[off]     = v0;
                C[off + 1] = v1;
            }
        }
}

// ---------------- propagation ----------------
__global__ void __launch_bounds__(256) prop_kernel(
    const float* __restrict__ hsrc, const float* __restrict__ h0,
    float* __restrict__ hdst)
{
    int warp = (blockIdx.x * blockDim.x + threadIdx.x) >> 5;
    if (warp >= NN) return;
    int lane = threadIdx.x & 31;
    int half = lane >> 4;
    int sub  = lane & 15;

    int beg = g_rowoff[warp];
    int end = g_rowoff[warp + 1];

    float4 acc = make_float4(0.f, 0.f, 0.f, 0.f);
    for (int idx = beg + half; idx < end; idx += 2) {
        int2 ed = g_edge[idx];
        float w = __int_as_float(ed.y);
        float4 hv = *(const float4*)(hsrc + (size_t)ed.x * OUTD + sub * 4);
        acc.x = fmaf(hv.x, w, acc.x);
        acc.y = fmaf(hv.y, w, acc.y);
        acc.z = fmaf(hv.z, w, acc.z);
        acc.w = fmaf(hv.w, w, acc.w);
    }
    __syncwarp();
    acc.x += __shfl_down_sync(0xffffffffu, acc.x, 16);
    acc.y += __shfl_down_sync(0xffffffffu, acc.y, 16);
    acc.z += __shfl_down_sync(0xffffffffu, acc.z, 16);
    acc.w += __shfl_down_sync(0xffffffffu, acc.w, 16);

    if (half == 0) {
        float4 h0v = *(const float4*)(h0 + (size_t)warp * OUTD + sub * 4);
        float4 outv;
        outv.x = acc.x + ALPHA * h0v.x;
        outv.y = acc.y + ALPHA * h0v.y;
        outv.z = acc.z + ALPHA * h0v.z;
        outv.w = acc.w + ALPHA * h0v.w;
        *(float4*)(hdst + (size_t)warp * OUTD + sub * 4) = outv;
    }
}

// ---------------- host launcher ----------------
extern "C" void kernel_launch(void* const* d_in, const int* in_sizes, int n_in,
                              void* d_out, int out_size)
{
    const float* x    = (const float*)d_in[0];
    const float* W1   = (const float*)d_in[1];
    const float* b1   = (const float*)d_in[2];
    const float* W2   = (const float*)d_in[3];
    const float* b2   = (const float*)d_in[4];
    const float* W3   = (const float*)d_in[5];
    const float* b3   = (const float*)d_in[6];
    const float* ew   = (const float*)d_in[7];
    const int*   erow = (const int*)d_in[8];
    const int*   ecol = (const int*)d_in[9];

    float *h0, *hA, *hB;
    __half *h1f, *b1f, *b2f;
    __nv_bfloat16 *h2h, *h2l, *b3h, *b3l;
    cudaGetSymbolAddress((void**)&h1f, g_h1f);
    cudaGetSymbolAddress((void**)&h2h, g_h2h);
    cudaGetSymbolAddress((void**)&h2l, g_h2l);
    cudaGetSymbolAddress((void**)&h0, g_h0);
    cudaGetSymbolAddress((void**)&hA, g_hA);
    cudaGetSymbolAddress((void**)&hB, g_hB);
    cudaGetSymbolAddress((void**)&b1f, g_B1f);
    cudaGetSymbolAddress((void**)&b2f, g_B2f);
    cudaGetSymbolAddress((void**)&b3h, g_B3h);
    cudaGetSymbolAddress((void**)&b3l, g_B3l);

    cudaFuncSetAttribute(gemm_fp16_kernel<256, true, true,  true >, cudaFuncAttributeMaxDynamicSharedMemorySize, F_SMEM);
    cudaFuncSetAttribute(gemm_fp16_kernel<256, true, false, false>, cudaFuncAttributeMaxDynamicSharedMemorySize, F_SMEM);
    cudaFuncSetAttribute(gemm_bf16x3_kernel<64, false>, cudaFuncAttributeMaxDynamicSharedMemorySize, GEMM_SMEM);

    // --- weight prep ---
    w_fp16_kernel<<<(HID * KPAD1 + 255) / 256, 256>>>(W1, b1f, IN_DIM, HID, KPAD1);
    w_fp16_kernel<<<(HID * HID + 255) / 256, 256>>>(W2, b2f, HID, HID, HID);
    splitw_bf16_kernel<<<(OUTD * HID + 255) / 256, 256>>>(W3, b3h, b3l, HID, OUTD, HID);

    // --- MLP ---
    // GEMM1: fp32 x -> fp16 h1 (1-term fp16 MMA)
    gemm_fp16_kernel<256, true, true,  true ><<<dim3(NN / 128, 4), 256, F_SMEM>>>(
        x, nullptr, b1f, b1, h1f, nullptr, nullptr, IN_DIM, KPAD1);
    // GEMM2: fp16 h1 -> split-bf16 h2 (1-term fp16 MMA)
    gemm_fp16_kernel<256, true, false, false><<<dim3(NN / 128, 4), 256, F_SMEM>>>(
        nullptr, h1f, b2f, b2, nullptr, h2h, h2l, HID, HID);
    // GEMM3: split-bf16 h2 -> fp32 h0 (3-term bf16 MMA, accurate)
    gemm_bf16x3_kernel<64, false><<<dim3(NN / 128, 1), 256, GEMM_SMEM>>>(
        h2h, h2l, b3h, b3l, b3, h0, HID);

    // --- CSR build ---
    zero_cursor_kernel<<<NN / 256, 256>>>();
    hist_kernel<<<EE / 256, 256>>>(erow);
    scan_kernel<<<1, 1024>>>();
    scatter_kernel<<<EE / 256, 256>>>(erow, ecol, ew);

    // --- K=10 propagation steps ---
    float* out = (float*)d_out;
    const float* src = h0;
    for (int s = 0; s < 10; s++) {
        float* dst = (s == 9) ? out : ((s & 1) ? hB : hA);
        prop_kernel<<<(NN * 32) / 256, 256>>>(src, h0, dst);
        src = dst;
    }
}

// round 10
// speedup vs baseline: 1.1935x; 1.0423x over previous
#include <cuda_runtime.h>
#include <cuda_bf16.h>
#include <cuda_fp16.h>
#include <cstdint>

#define NN      65536
#define EE      1048576
#define IN_DIM  500
#define KPAD1   512
#define HID     256
#define OUTD    64
#define ALPHA   0.1f

// ---------------- static device scratch ----------------
__device__ __half g_h1f[(size_t)NN * HID];     // layer-1 out, fp16
__device__ __half g_h2f[(size_t)NN * HID];     // layer-2 out, fp16
__device__ float g_h0[(size_t)NN * OUTD];
__device__ float g_hA[(size_t)NN * OUTD];
__device__ float g_hB[(size_t)NN * OUTD];
__device__ __half g_B1f[(size_t)HID * KPAD1];
__device__ __half g_B2f[(size_t)HID * HID];
__device__ __half g_B3f[(size_t)OUTD * HID];
__device__ int   g_rowoff[NN + 1];
__device__ int   g_cursor[NN];
__device__ int2  g_edge[EE];

// ---------------- helpers ----------------
__device__ __forceinline__ uint32_t smem_to_u32(const void* p) {
    uint32_t a;
    asm("{ .reg .u64 t; cvta.to.shared.u64 t, %1; cvt.u32.u64 %0, t; }" : "=r"(a) : "l"(p));
    return a;
}
__device__ __forceinline__ void ldmatrix_x4(uint32_t* r, uint32_t addr) {
    asm volatile("ldmatrix.sync.aligned.m8n8.x4.shared.b16 {%0,%1,%2,%3}, [%4];"
                 : "=r"(r[0]), "=r"(r[1]), "=r"(r[2]), "=r"(r[3]) : "r"(addr));
}
__device__ __forceinline__ void mma_fp16(float* c, const uint32_t* a, const uint32_t* b) {
    asm volatile(
        "mma.sync.aligned.m16n8k16.row.col.f32.f16.f16.f32 "
        "{%0,%1,%2,%3}, {%4,%5,%6,%7}, {%8,%9}, {%0,%1,%2,%3};"
        : "+f"(c[0]), "+f"(c[1]), "+f"(c[2]), "+f"(c[3])
        : "r"(a[0]), "r"(a[1]), "r"(a[2]), "r"(a[3]), "r"(b[0]), "r"(b[1]));
}
__device__ __forceinline__ uint32_t pack_h16(__half x0, __half x1) {
    return ((uint32_t)__half_as_ushort(x1) << 16) | (uint32_t)__half_as_ushort(x0);
}

// ---------------- CSR construction ----------------
__global__ void zero_cursor_kernel() {
    int i = blockIdx.x * blockDim.x + threadIdx.x;
    if (i < NN) g_cursor[i] = 0;
}
__global__ void hist_kernel(const int* __restrict__ row) {
    int e = blockIdx.x * blockDim.x + threadIdx.x;
    if (e < EE) atomicAdd(&g_cursor[row[e]], 1);
}
__global__ void scan_kernel() {
    __shared__ int s[1024];
    int t = threadIdx.x;
    int base = t * 64;
    int sum = 0;
#pragma unroll 8
    for (int i = 0; i < 64; i++) sum += g_cursor[base + i];
    s[t] = sum;
    __syncthreads();
    for (int off = 1; off < 1024; off <<= 1) {
        int v = (t >= off) ? s[t - off] : 0;
        __syncthreads();
        s[t] += v;
        __syncthreads();
    }
    int running = s[t] - sum;
    for (int i = 0; i < 64; i++) {
        int d = g_cursor[base + i];
        g_rowoff[base + i] = running;
        g_cursor[base + i] = running;
        running += d;
    }
    if (t == 1023) g_rowoff[NN] = s[1023];
}
__global__ void scatter_kernel(const int* __restrict__ row, const int* __restrict__ col,
                               const float* __restrict__ w) {
    int e = blockIdx.x * blockDim.x + threadIdx.x;
    if (e < EE) {
        int p = atomicAdd(&g_cursor[row[e]], 1);
        g_edge[p] = make_int2(col[e], __float_as_int(0.9f * w[e]));
    }
}

// ---------------- weight prep: transpose + pad to fp16 ----------------
__global__ void w_fp16_kernel(const float* __restrict__ W, __half* __restrict__ Bf,
                              int K, int N, int Kpad) {
    int idx = blockIdx.x * blockDim.x + threadIdx.x;
    if (idx >= N * Kpad) return;
    int n = idx / Kpad, k = idx - n * Kpad;
    float v = (k < K) ? W[(size_t)k * N + n] : 0.f;
    Bf[idx] = __float2half_rn(v);
}

// ================= fp16 single-term GEMM, warp tile 32x64 =================
// CTA tile 128 x (64*NWN). 4 m-warps x NWN n-warps, 128*NWN threads.
// BK=32, double-buffered smem (80B row stride).
// A_FP32_IN: A fp32 [.,K] (convert in-kernel); else A fp16 [.,Kpad].
// OUT_FP32:  C fp32; else C fp16.
template <int NMAT, int NWN, bool RELU, bool A_FP32_IN, bool OUT_FP32>
__global__ void __launch_bounds__(128 * NWN, (NWN == 1) ? 2 : 1)
gemm_fp16_kernel(
    const float* __restrict__ A, const __half* __restrict__ Af,
    const __half* __restrict__ Bf, const float* __restrict__ bias,
    float* __restrict__ C, __half* __restrict__ Cf,
    int K, int Kpad)
{
    constexpr int NTH  = 128 * NWN;
    constexpr int NT   = 64 * NWN;
    constexpr int A_B  = 128 * 80;          // A tile bytes (10240)
    constexpr int B_B  = NT * 80;           // B tile bytes
    constexpr int BUF  = A_B + B_B;
    constexpr int AF32 = 1024 / NTH;        // fp32-A float4 slots/thread
    constexpr int ASP  = 512 / NTH;         // fp16-A uint4 slots/thread

    extern __shared__ char smem[];
    uint32_t sbase = smem_to_u32(smem);

    int tid  = threadIdx.x;
    int wid  = tid >> 5;
    int lane = tid & 31;
    int m0 = blockIdx.x * 128;
    int n0 = blockIdx.y * NT;
    int warp_m = wid & 3;
    int warp_n = wid >> 2;

    float acc[2][8][4];
#pragma unroll
    for (int i = 0; i < 2; i++)
#pragma unroll
        for (int j = 0; j < 8; j++)
#pragma unroll
            for (int r = 0; r < 4; r++) acc[i][j][r] = 0.f;

    const int nch = Kpad >> 5;

    float4 ga[AF32];
    uint4  gaf[ASP];
    uint4  gb[2];

#define F_LOAD(CH) do { \
    int k0_ = (CH) << 5; \
    if (A_FP32_IN) { \
        _Pragma("unroll") \
        for (int i = 0; i < AF32; i++) { \
            int slot = tid + i * NTH; \
            int kg = k0_ + (slot & 7) * 4; \
            if (kg + 3 < K) ga[i] = *(const float4*)(A + (size_t)(m0 + (slot >> 3)) * K + kg); \
            else            ga[i] = make_float4(0.f, 0.f, 0.f, 0.f); \
        } \
    } else { \
        _Pragma("unroll") \
        for (int i = 0; i < ASP; i++) { \
            int slot = tid + i * NTH; \
            gaf[i] = *(const uint4*)(Af + (size_t)(m0 + (slot >> 2)) * Kpad + k0_ + (slot & 3) * 8); \
        } \
    } \
    _Pragma("unroll") \
    for (int i = 0; i < 2; i++) { \
        int slot = tid + i * NTH; \
        gb[i] = *(const uint4*)(Bf + (size_t)(n0 + (slot >> 2)) * Kpad + k0_ + (slot & 3) * 8); \
    } \
} while (0)

#define F_STORE(BUFI) do { \
    char* tb = smem + (BUFI) * BUF; \
    if (A_FP32_IN) { \
        _Pragma("unroll") \
        for (int i = 0; i < AF32; i++) { \
            int slot = tid + i * NTH; \
            uint2 p_; \
            p_.x = pack_h16(__float2half_rn(ga[i].x), __float2half_rn(ga[i].y)); \
            p_.y = pack_h16(__float2half_rn(ga[i].z), __float2half_rn(ga[i].w)); \
            *(uint2*)(tb + (slot >> 3) * 80 + (slot & 7) * 8) = p_; \
        } \
    } else { \
        _Pragma("unroll") \
        for (int i = 0; i < ASP; i++) { \
            int slot = tid + i * NTH; \
            *(uint4*)(tb + (slot >> 2) * 80 + (slot & 3) * 16) = gaf[i]; \
        } \
    } \
    _Pragma("unroll") \
    for (int i = 0; i < 2; i++) { \
        int slot = tid + i * NTH; \
        *(uint4*)(tb + A_B + (slot >> 2) * 80 + (slot & 3) * 16) = gb[i]; \
    } \
} while (0)

    F_LOAD(0);
    F_STORE(0);
    __syncthreads();

    for (int ch = 0; ch < nch; ch++) {
        if (ch + 1 < nch) F_LOAD(ch + 1);

        uint32_t ub = sbase + (ch & 1) * BUF;
#pragma unroll
        for (int kk = 0; kk < 32; kk += 16) {
            uint32_t afr[2][4];
            uint32_t bfr[4][4];
            {
                int rowA = warp_m * 32 + (lane & 15);
                int colA = kk + ((lane >> 4) << 3);
#pragma unroll
                for (int mt = 0; mt < 2; mt++)
                    ldmatrix_x4(afr[mt], ub + (uint32_t)((rowA + mt * 16) * 80 + colA * 2));
                int rowB = warp_n * 64 + ((lane >> 4) << 3) + (lane & 7);
                int colB = kk + (((lane >> 3) & 1) << 3);
#pragma unroll
                for (int np = 0; np < 4; np++)
                    ldmatrix_x4(bfr[np], ub + (uint32_t)(A_B + (rowB + np * 16) * 80 + colB * 2));
            }
#pragma unroll
            for (int mt = 0; mt < 2; mt++)
#pragma unroll
                for (int nt = 0; nt < 8; nt++) {
                    int np = nt >> 1, sub = (nt & 1) * 2;
                    mma_fp16(acc[mt][nt], afr[mt], &bfr[np][sub]);
                }
        }
        __syncthreads();
        if (ch + 1 < nch) {
            F_STORE((ch + 1) & 1);
        }
        __syncthreads();
    }

    // ---- epilogue ----
    int rb   = m0 + warp_m * 32 + (lane >> 2);
    int colb = n0 + warp_n * 64 + (lane & 3) * 2;
#pragma unroll
    for (int mt = 0; mt < 2; mt++)
#pragma unroll
        for (int nt = 0; nt < 8; nt++) {
            int col = colb + nt * 8;
            float b0 = __ldg(bias + col);
            float b1 = __ldg(bias + col + 1);
#pragma unroll
            for (int rp = 0; rp < 2; rp++) {
                int row = rb + mt * 16 + rp * 8;
                float v0 = acc[mt][nt][rp * 2 + 0] + b0;
                float v1 = acc[mt][nt][rp * 2 + 1] + b1;
                if (RELU) { v0 = fmaxf(v0, 0.f); v1 = fmaxf(v1, 0.f); }
                size_t off = (size_t)row * NMAT + col;
                if (OUT_FP32) {
                    C[off]     = v0;
                    C[off + 1] = v1;
                } else {
                    *(uint32_t*)(Cf + off) = pack_h16(__float2half_rn(v0), __float2half_rn(v1));
                }
            }
        }
}

// ---------------- propagation: warp = row, four 8-lane groups (MLP=4) ----------------
// hdst[r] = sum_e h[col(e)]*(0.9*w(e)) + 0.1 * h0[r]
__global__ void __launch_bounds__(256) prop_kernel(
    const float* __restrict__ hsrc, const float* __restrict__ h0,
    float* __restrict__ hdst)
{
    int warp = (blockIdx.x * blockDim.x + threadIdx.x) >> 5;
    if (warp >= NN) return;
    int lane = threadIdx.x & 31;
    int q   = lane >> 3;          // 0..3: edge stripe
    int sub = lane & 7;           // 8 lanes x 8 channels

    int beg = g_rowoff[warp];
    int end = g_rowoff[warp + 1];

    float4 a0 = make_float4(0.f, 0.f, 0.f, 0.f);
    float4 a1 = make_float4(0.f, 0.f, 0.f, 0.f);
    int idx = beg + q;
    if (idx < end) {
        int2 ed = __ldg(&g_edge[idx]);
        while (true) {
            int nidx = idx + 4;
            bool more = (nidx < end);
            int2 edn;
            if (more) edn = __ldg(&g_edge[nidx]);     // prefetch
            float w = __int_as_float(ed.y);
            const float* hp = hsrc + (size_t)ed.x * OUTD + sub * 8;
            float4 h0v = *(const float4*)hp;
            float4 h1v = *(const float4*)(hp + 4);
            a0.x = fmaf(h0v.x, w, a0.x);
            a0.y = fmaf(h0v.y, w, a0.y);
            a0.z = fmaf(h0v.z, w, a0.z);
            a0.w = fmaf(h0v.w, w, a0.w);
            a1.x = fmaf(h1v.x, w, a1.x);
            a1.y = fmaf(h1v.y, w, a1.y);
            a1.z = fmaf(h1v.z, w, a1.z);
            a1.w = fmaf(h1v.w, w, a1.w);
            if (!more) break;
            ed = edn;
            idx = nidx;
        }
    }
    __syncwarp();
    // reduce over q: lanes sub, sub+8, sub+16, sub+24
    a0.x += __shfl_down_sync(0xffffffffu, a0.x, 16);
    a0.y += __shfl_down_sync(0xffffffffu, a0.y, 16);
    a0.z += __shfl_down_sync(0xffffffffu, a0.z, 16);
    a0.w += __shfl_down_sync(0xffffffffu, a0.w, 16);
    a1.x += __shfl_down_sync(0xffffffffu, a1.x, 16);
    a1.y += __shfl_down_sync(0xffffffffu, a1.y, 16);
    a1.z += __shfl_down_sync(0xffffffffu, a1.z, 16);
    a1.w += __shfl_down_sync(0xffffffffu, a1.w, 16);
    a0.x += __shfl_down_sync(0xffffffffu, a0.x, 8);
    a0.y += __shfl_down_sync(0xffffffffu, a0.y, 8);
    a0.z += __shfl_down_sync(0xffffffffu, a0.z, 8);
    a0.w += __shfl_down_sync(0xffffffffu, a0.w, 8);
    a1.x += __shfl_down_sync(0xffffffffu, a1.x, 8);
    a1.y += __shfl_down_sync(0xffffffffu, a1.y, 8);
    a1.z += __shfl_down_sync(0xffffffffu, a1.z, 8);
    a1.w += __shfl_down_sync(0xffffffffu, a1.w, 8);

    if (lane < 8) {
        const float* h0p = h0 + (size_t)warp * OUTD + sub * 8;
        float4 b0 = *(const float4*)h0p;
        float4 b1 = *(const float4*)(h0p + 4);
        float4 o0, o1;
        o0.x = a0.x + ALPHA * b0.x;
        o0.y = a0.y + ALPHA * b0.y;
        o0.z = a0.z + ALPHA * b0.z;
        o0.w = a0.w + ALPHA * b0.w;
        o1.x = a1.x + ALPHA * b1.x;
        o1.y = a1.y + ALPHA * b1.y;
        o1.z = a1.z + ALPHA * b1.z;
        o1.w = a1.w + ALPHA * b1.w;
        float* dp = hdst + (size_t)warp * OUTD + sub * 8;
        *(float4*)dp       = o0;
        *(float4*)(dp + 4) = o1;
    }
}

// ---------------- host launcher ----------------
extern "C" void kernel_launch(void* const* d_in, const int* in_sizes, int n_in,
                              void* d_out, int out_size)
{
    const float* x    = (const float*)d_in[0];
    const float* W1   = (const float*)d_in[1];
    const float* b1   = (const float*)d_in[2];
    const float* W2   = (const float*)d_in[3];
    const float* b2   = (const float*)d_in[4];
    const float* W3   = (const float*)d_in[5];
    const float* b3   = (const float*)d_in[6];
    const float* ew   = (const float*)d_in[7];
    const int*   erow = (const int*)d_in[8];
    const int*   ecol = (const int*)d_in[9];

    float *h0, *hA, *hB;
    __half *h1f, *h2f, *b1f, *b2f, *b3f;
    cudaGetSymbolAddress((void**)&h1f, g_h1f);
    cudaGetSymbolAddress((void**)&h2f, g_h2f);
    cudaGetSymbolAddress((void**)&h0, g_h0);
    cudaGetSymbolAddress((void**)&hA, g_hA);
    cudaGetSymbolAddress((void**)&hB, g_hB);
    cudaGetSymbolAddress((void**)&b1f, g_B1f);
    cudaGetSymbolAddress((void**)&b2f, g_B2f);
    cudaGetSymbolAddress((void**)&b3f, g_B3f);

    // smem: NWN=4 -> (10240+20480)*2 = 61440 ; NWN=1 -> (10240+5120)*2 = 30720
    const int SMEM_N4 = 2 * (10240 + 20480);
    const int SMEM_N1 = 2 * (10240 + 5120);
    cudaFuncSetAttribute(gemm_fp16_kernel<256, 4, true,  true,  false>, cudaFuncAttributeMaxDynamicSharedMemorySize, SMEM_N4);
    cudaFuncSetAttribute(gemm_fp16_kernel<256, 4, true,  false, false>, cudaFuncAttributeMaxDynamicSharedMemorySize, SMEM_N4);
    cudaFuncSetAttribute(gemm_fp16_kernel<64,  1, false, false, true >, cudaFuncAttributeMaxDynamicSharedMemorySize, SMEM_N1);

    // --- weight prep (3 launches keep GEMM1 in ncu's capture slot) ---
    w_fp16_kernel<<<(HID * KPAD1 + 255) / 256, 256>>>(W1, b1f, IN_DIM, HID, KPAD1);
    w_fp16_kernel<<<(HID * HID + 255) / 256, 256>>>(W2, b2f, HID, HID, HID);
    w_fp16_kernel<<<(OUTD * HID + 255) / 256, 256>>>(W3, b3f, HID, OUTD, HID);

    // --- MLP (fp16 MMA, fp32 accumulate) ---
    // GEMM1: fp32 x -> fp16 h1, CTA 128x256 (x read once)
    gemm_fp16_kernel<256, 4, true,  true,  false><<<dim3(NN / 128, 1), 512, SMEM_N4>>>(
        x, nullptr, b1f, b1, nullptr, h1f, IN_DIM, KPAD1);
    // GEMM2: fp16 h1 -> fp16 h2, CTA 128x256
    gemm_fp16_kernel<256, 4, true,  false, false><<<dim3(NN / 128, 1), 512, SMEM_N4>>>(
        nullptr, h1f, b2f, b2, nullptr, h2f, HID, HID);
    // GEMM3: fp16 h2 -> fp32 h0, CTA 128x64
    gemm_fp16_kernel<64,  1, false, false, true ><<<dim3(NN / 128, 1), 128, SMEM_N1>>>(
        nullptr, h2f, b3f, b3, h0, nullptr, HID, HID);

    // --- CSR build ---
    zero_cursor_kernel<<<NN / 256, 256>>>();
    hist_kernel<<<EE / 256, 256>>>(erow);
    scan_kernel<<<1, 1024>>>();
    scatter_kernel<<<EE / 256, 256>>>(erow, ecol, ew);

    // --- K=10 propagation steps ---
    float* out = (float*)d_out;
    const float* src = h0;
    for (int s = 0; s < 10; s++) {
        float* dst = (s == 9) ? out : ((s & 1) ? hB : hA);
        prop_kernel<<<(NN * 32) / 256, 256>>>(src, h0, dst);
        src = dst;
    }
}